// round 5
// baseline (speedup 1.0000x reference)
#include <cuda_runtime.h>
#include <cstdint>
#include <cstddef>

// Sinkhorn factored form: y = diag(r) * A * diag(c),  A = exp(x)+eps constant.
//   r <- 1/(A c);  c <- 1/(A^T r)
// 16 matrices of 512x512 fp32; one 8-CTA cluster per matrix; A register-resident.
// R5: ONE communication phase per iteration — all-to-all broadcast of column
//     partials (st.async.b64), double-buffered mbarriers, redundant c compute.

#define N_ITERS 100
#define NDIM 512
#define TX_BYTES 16384   // 8 sources * 256 pairs * 8B per phase

__device__ __forceinline__ uint32_t smem_u32(const void* p) {
    return (uint32_t)__cvta_generic_to_shared(p);
}
__device__ __forceinline__ uint32_t mapa_u32(uint32_t addr, uint32_t rank) {
    uint32_t r;
    asm("mapa.shared::cluster.u32 %0, %1, %2;" : "=r"(r) : "r"(addr), "r"(rank));
    return r;
}
__device__ __forceinline__ void fma2(uint64_t& d, uint64_t a, uint64_t b, uint64_t c) {
    asm("fma.rn.f32x2 %0, %1, %2, %3;" : "=l"(d) : "l"(a), "l"(b), "l"(c));
}
__device__ __forceinline__ void add2(uint64_t& d, uint64_t a, uint64_t b) {
    asm("add.rn.f32x2 %0, %1, %2;" : "=l"(d) : "l"(a), "l"(b));
}
__device__ __forceinline__ uint64_t pack2(float lo, float hi) {
    uint64_t r;
    asm("mov.b64 %0, {%1, %2};" : "=l"(r) : "f"(lo), "f"(hi));
    return r;
}
__device__ __forceinline__ void unpack2(float& lo, float& hi, uint64_t v) {
    asm("mov.b64 {%0, %1}, %2;" : "=f"(lo), "=f"(hi) : "l"(v));
}
__device__ __forceinline__ void st_async_b64(uint32_t dst, uint64_t v, uint32_t mbar) {
    asm volatile(
        "st.async.shared::cluster.mbarrier::complete_tx::bytes.b64 [%0], %1, [%2];"
        :: "r"(dst), "l"(v), "r"(mbar) : "memory");
}
__device__ __forceinline__ void mbar_init(uint32_t addr, uint32_t cnt) {
    asm volatile("mbarrier.init.shared.b64 [%0], %1;" :: "r"(addr), "r"(cnt) : "memory");
}
__device__ __forceinline__ void mbar_expect_tx(uint32_t addr, uint32_t bytes) {
    asm volatile("mbarrier.arrive.expect_tx.shared.b64 _, [%0], %1;"
                 :: "r"(addr), "r"(bytes) : "memory");
}
__device__ __forceinline__ void mbar_wait_cluster(uint32_t addr, uint32_t parity) {
    uint32_t done = 0;
    while (!done) {
        asm volatile(
            "{\n\t.reg .pred p;\n\t"
            "mbarrier.try_wait.parity.acquire.cluster.shared::cta.b64 p, [%1], %2, 0x989680;\n\t"
            "selp.b32 %0, 1, 0, p;\n\t}"
            : "=r"(done) : "r"(addr), "r"(parity) : "memory");
    }
}
#define CLUSTER_SYNC() do { \
    asm volatile("barrier.cluster.arrive.aligned;" ::: "memory"); \
    asm volatile("barrier.cluster.wait.aligned;"   ::: "memory"); } while (0)

__global__ void __launch_bounds__(512, 1) __cluster_dims__(8, 1, 1)
sinkhorn_kernel(const float* __restrict__ x, float* __restrict__ out)
{
    __shared__ __align__(16) float    c_smem[NDIM];        // column scaling c
    __shared__ __align__(16) uint64_t prow[16][256];       // per-warp col partials (f32x2)
    __shared__ __align__(16) uint64_t allpart[2][8][256];  // double-buffered all-to-all rx
    __shared__ __align__(8)  uint64_t mbars[2];            // one mbar per buffer

    const int tid  = threadIdx.x;
    const int warp = tid >> 5;            // 0..15
    const int lane = tid & 31;
    const int rank = blockIdx.x & 7;      // CTA rank in cluster = row block
    const int bmat = blockIdx.x >> 3;     // matrix index 0..15

    const int row0 = rank * 64 + warp * 4;      // 4 rows per warp
    // thread covers col pairs (64q + 2*lane, +1) == f32x2 index 32q+lane, q=0..7

    // ---------------- Prologue: A = exp(x) + eps, packed f32x2 in regs -------
    uint64_t a2[4][8];
    const float* xbase = x + ((size_t)bmat * NDIM + row0) * NDIM;
    #pragma unroll
    for (int p = 0; p < 4; p++) {
        const float2* xrow = (const float2*)(xbase + (size_t)p * NDIM) + lane;
        #pragma unroll
        for (int q = 0; q < 8; q++) {
            float2 v = xrow[32 * q];
            a2[p][q] = pack2(expf(v.x) + 0.001f, expf(v.y) + 0.001f);
        }
    }

    const uint32_t mbar_base = smem_u32(&mbars[0]);
    const uint32_t ap_base   = smem_u32(&allpart[0][0][0]);

    c_smem[tid] = 1.0f;
    if (tid == 0) {
        mbar_init(mbar_base, 1);
        mbar_init(mbar_base + 8, 1);
        mbar_expect_tx(mbar_base, TX_BYTES);     // arm buffer 0 / iteration 0
    }
    __syncthreads();
    CLUSTER_SYNC();   // all barriers live + armed before any st.async

    // loop-invariant send destinations: thread sends pair p=tid&255 to 4 dests
    const uint32_t pr  = (uint32_t)(tid & 255);
    const int      jb  = (tid >> 8) * 4;
    uint32_t send_base[4], mbar_dst[4];
    #pragma unroll
    for (int j = 0; j < 4; j++) {
        uint32_t d = (uint32_t)(jb + j);
        send_base[j] = mapa_u32(ap_base + (uint32_t)rank * 2048u + pr * 8u, d);
        mbar_dst[j]  = mapa_u32(mbar_base, d);
    }

    const uint64_t* c2 = (const uint64_t*)c_smem;
    float r[4];

    for (int it = 0; it < N_ITERS; it++) {
        const uint32_t buf    = (uint32_t)(it & 1);
        const uint32_t parity = (uint32_t)((it >> 1) & 1);

        // ---- step 1: row sums acc_i = (A c)_i ; r = 1/acc  (CTA-local) ----
        uint64_t acc2[4];
        #pragma unroll
        for (int p = 0; p < 4; p++) acc2[p] = 0ull;
        #pragma unroll
        for (int q = 0; q < 8; q++) {
            uint64_t cq = c2[32 * q + lane];
            #pragma unroll
            for (int p = 0; p < 4; p++) fma2(acc2[p], a2[p][q], cq, acc2[p]);
        }
        float acc[4];
        #pragma unroll
        for (int p = 0; p < 4; p++) {
            float lo, hi; unpack2(lo, hi, acc2[p]);
            acc[p] = lo + hi;
        }
        #pragma unroll
        for (int off = 16; off > 0; off >>= 1) {
            #pragma unroll
            for (int p = 0; p < 4; p++)
                acc[p] += __shfl_xor_sync(0xffffffffu, acc[p], off);
        }
        #pragma unroll
        for (int p = 0; p < 4; p++) r[p] = 1.0f / acc[p];

        // ---- step 2: column partials over this warp's 4 rows (f32x2) --------
        uint64_t r2[4];
        #pragma unroll
        for (int p = 0; p < 4; p++) r2[p] = pack2(r[p], r[p]);
        #pragma unroll
        for (int q = 0; q < 8; q++) {
            uint64_t s2 = 0ull;
            #pragma unroll
            for (int p = 0; p < 4; p++) fma2(s2, r2[p], a2[p][q], s2);
            prow[warp][32 * q + lane] = s2;
        }
        __syncthreads();   // (A) prow ready; prior allpart reads all complete

        // re-arm NEXT buffer before our sends (peers' next-iter sends to us are
        // transitively gated by our sends below, so re-arm always wins the race)
        if (tid == 0) mbar_expect_tx(mbar_base + ((buf ^ 1u) * 8u), TX_BYTES);

        // ---- step 3: reduce 16 warps for pair pr, broadcast to 4 dests ------
        {
            uint64_t s2 = prow[0][pr];
            #pragma unroll
            for (int w = 1; w < 16; w++) add2(s2, s2, prow[w][pr]);
            const uint32_t bufoff = buf * (uint32_t)TX_BYTES;
            #pragma unroll
            for (int j = 0; j < 4; j++)
                st_async_b64(send_base[j] + bufoff, s2, mbar_dst[j] + buf * 8u);
        }

        // ---- step 4: wait for all 8 CTAs' partials, compute c locally -------
        mbar_wait_cluster(mbar_base + buf * 8u, parity);
        {
            const float* ap = (const float*)&allpart[buf][0][0];
            float s = 0.0f;
            #pragma unroll
            for (int rr = 0; rr < 8; rr++) s += ap[rr * 512 + tid];
            c_smem[tid] = 1.0f / s;
        }
        __syncthreads();   // (B) c ready for next step 1
    }

    CLUSTER_SYNC();   // quiesce cluster before teardown

    // ---------------- Epilogue: y_ij = r_i * A_ij * c_j ----------------------
    float* obase = out + ((size_t)bmat * NDIM + row0) * NDIM;
    #pragma unroll
    for (int p = 0; p < 4; p++) {
        float2* orow = (float2*)(obase + (size_t)p * NDIM) + lane;
        #pragma unroll
        for (int q = 0; q < 8; q++) {
            float alo, ahi; unpack2(alo, ahi, a2[p][q]);
            float2 cv = ((const float2*)c_smem)[32 * q + lane];
            float2 o;
            o.x = r[p] * alo * cv.x;
            o.y = r[p] * ahi * cv.y;
            orow[32 * q] = o;
        }
    }
}

extern "C" void kernel_launch(void* const* d_in, const int* in_sizes, int n_in,
                              void* d_out, int out_size)
{
    (void)in_sizes; (void)n_in; (void)out_size;
    const float* x = (const float*)d_in[0];
    float* out = (float*)d_out;
    // 16 matrices * 8 CTAs = 128 CTAs; __cluster_dims__(8) groups them per matrix.
    sinkhorn_kernel<<<128, 512>>>(x, out);
}

// round 6
// speedup vs baseline: 1.0861x; 1.0861x over previous
#include <cuda_runtime.h>
#include <cstdint>
#include <cstddef>

// Sinkhorn factored form: y = diag(r) * A * diag(c),  A = exp(x)+eps constant.
//   r <- 1/(A c);  c <- 1/(A^T r)
// 16 matrices of 512x512 fp32; one 8-CTA cluster per matrix; A register-resident.
// R6: two-hop exchange as in R4, but scalar st.async (4096 msgs/cluster-iter)
//     replaced by cp.async.bulk cluster copies (128 msgs/cluster-iter, 256B each).

#define N_ITERS 100
#define NDIM 512
#define SEG_BYTES 256        // 64 floats per owner segment
#define HOP_TX    2048       // 8 senders * 256B per hop

__device__ __forceinline__ uint32_t smem_u32(const void* p) {
    return (uint32_t)__cvta_generic_to_shared(p);
}
__device__ __forceinline__ uint32_t mapa_u32(uint32_t addr, uint32_t rank) {
    uint32_t r;
    asm("mapa.shared::cluster.u32 %0, %1, %2;" : "=r"(r) : "r"(addr), "r"(rank));
    return r;
}
__device__ __forceinline__ void fma2(uint64_t& d, uint64_t a, uint64_t b, uint64_t c) {
    asm("fma.rn.f32x2 %0, %1, %2, %3;" : "=l"(d) : "l"(a), "l"(b), "l"(c));
}
__device__ __forceinline__ void add2(uint64_t& d, uint64_t a, uint64_t b) {
    asm("add.rn.f32x2 %0, %1, %2;" : "=l"(d) : "l"(a), "l"(b));
}
__device__ __forceinline__ uint64_t pack2(float lo, float hi) {
    uint64_t r;
    asm("mov.b64 %0, {%1, %2};" : "=l"(r) : "f"(lo), "f"(hi));
    return r;
}
__device__ __forceinline__ void unpack2(float& lo, float& hi, uint64_t v) {
    asm("mov.b64 {%0, %1}, %2;" : "=f"(lo), "=f"(hi) : "l"(v));
}
// bulk local-smem -> remote-smem copy, tx-counted on the remote CTA's mbarrier
__device__ __forceinline__ void blkcp_cluster(uint32_t dst, uint32_t src,
                                              uint32_t bytes, uint32_t mbar) {
    asm volatile(
        "cp.async.bulk.shared::cluster.shared::cta.mbarrier::complete_tx::bytes "
        "[%0], [%1], %2, [%3];"
        :: "r"(dst), "r"(src), "r"(bytes), "r"(mbar) : "memory");
}
__device__ __forceinline__ void fence_async_shared() {
    asm volatile("fence.proxy.async.shared::cta;" ::: "memory");
}
__device__ __forceinline__ void mbar_init(uint32_t addr, uint32_t cnt) {
    asm volatile("mbarrier.init.shared.b64 [%0], %1;" :: "r"(addr), "r"(cnt) : "memory");
}
__device__ __forceinline__ void mbar_expect_tx(uint32_t addr, uint32_t bytes) {
    asm volatile("mbarrier.arrive.expect_tx.shared.b64 _, [%0], %1;"
                 :: "r"(addr), "r"(bytes) : "memory");
}
__device__ __forceinline__ void mbar_wait_cluster(uint32_t addr, uint32_t parity) {
    uint32_t done = 0;
    while (!done) {
        asm volatile(
            "{\n\t.reg .pred p;\n\t"
            "mbarrier.try_wait.parity.acquire.cluster.shared::cta.b64 p, [%1], %2, 0x989680;\n\t"
            "selp.b32 %0, 1, 0, p;\n\t}"
            : "=r"(done) : "r"(addr), "r"(parity) : "memory");
    }
}
#define CLUSTER_SYNC() do { \
    asm volatile("barrier.cluster.arrive.aligned;" ::: "memory"); \
    asm volatile("barrier.cluster.wait.aligned;"   ::: "memory"); } while (0)

__global__ void __launch_bounds__(512, 1) __cluster_dims__(8, 1, 1)
sinkhorn_kernel(const float* __restrict__ x, float* __restrict__ out)
{
    __shared__ __align__(16) float    c_smem[NDIM];     // column scaling c (full 512)
    __shared__ __align__(16) uint64_t prow[16][256];    // per-warp col-pair partials
    __shared__ __align__(16) uint64_t myred[256];       // CTA-reduced partials (contig)
    __shared__ __align__(16) float    peer_part[8][64]; // [src CTA][my owned col]
    __shared__ __align__(16) float    c_own[64];        // new c for my owned cols
    __shared__ __align__(8)  uint64_t mbars[2];         // [0]=part, [1]=c

    const int tid  = threadIdx.x;
    const int warp = tid >> 5;            // 0..15
    const int lane = tid & 31;
    const int rank = blockIdx.x & 7;      // CTA rank in cluster = row block
    const int bmat = blockIdx.x >> 3;     // matrix index 0..15

    const int row0 = rank * 64 + warp * 4;      // 4 rows per warp
    // thread covers col pairs cp = 32q+lane (cols 2cp, 2cp+1), q = 0..7

    // ---------------- Prologue: A = exp(x) + eps, packed f32x2 in regs -------
    uint64_t a2[4][8];
    const float* xbase = x + ((size_t)bmat * NDIM + row0) * NDIM;
    #pragma unroll
    for (int p = 0; p < 4; p++) {
        const float2* xrow = (const float2*)(xbase + (size_t)p * NDIM) + lane;
        #pragma unroll
        for (int q = 0; q < 8; q++) {
            float2 v = xrow[32 * q];
            a2[p][q] = pack2(expf(v.x) + 0.001f, expf(v.y) + 0.001f);
        }
    }

    const uint32_t pm_addr    = smem_u32(&mbars[0]);
    const uint32_t cm_addr    = smem_u32(&mbars[1]);
    const uint32_t myred_a    = smem_u32(&myred[0]);
    const uint32_t peer_a     = smem_u32(&peer_part[0][0]);
    const uint32_t c_own_a    = smem_u32(&c_own[0]);
    const uint32_t c_smem_a   = smem_u32(&c_smem[0]);

    c_smem[tid] = 1.0f;
    if (tid == 0) {
        mbar_init(pm_addr, 1);
        mbar_init(cm_addr, 1);
        mbar_expect_tx(pm_addr, HOP_TX);   // arm iteration 0
        mbar_expect_tx(cm_addr, HOP_TX);
    }
    __syncthreads();
    CLUSTER_SYNC();   // all barriers live + armed before any bulk copy

    // loop-invariant bulk-copy endpoints for threads 0..7 (dest CTA = tid)
    const uint32_t dcta        = (uint32_t)(tid & 7);
    const uint32_t part_dst    = mapa_u32(peer_a  + (uint32_t)rank * SEG_BYTES, dcta);
    const uint32_t part_mbar_r = mapa_u32(pm_addr, dcta);
    const uint32_t part_src    = myred_a + dcta * SEG_BYTES;
    const uint32_t c_dst       = mapa_u32(c_smem_a + (uint32_t)rank * SEG_BYTES, dcta);
    const uint32_t c_mbar_r    = mapa_u32(cm_addr, dcta);

    const uint64_t* c2 = (const uint64_t*)c_smem;
    float r[4];

    for (int it = 0; it < N_ITERS; it++) {
        const uint32_t parity = (uint32_t)(it & 1);

        // ---- step 1: row sums acc_i = (A c)_i ; r = 1/acc  (CTA-local) ----
        uint64_t acc2[4];
        #pragma unroll
        for (int p = 0; p < 4; p++) acc2[p] = 0ull;
        #pragma unroll
        for (int q = 0; q < 8; q++) {
            uint64_t cq = c2[32 * q + lane];
            #pragma unroll
            for (int p = 0; p < 4; p++) fma2(acc2[p], a2[p][q], cq, acc2[p]);
        }
        float acc[4];
        #pragma unroll
        for (int p = 0; p < 4; p++) {
            float lo, hi; unpack2(lo, hi, acc2[p]);
            acc[p] = lo + hi;
        }
        #pragma unroll
        for (int off = 16; off > 0; off >>= 1) {
            #pragma unroll
            for (int p = 0; p < 4; p++)
                acc[p] += __shfl_xor_sync(0xffffffffu, acc[p], off);
        }
        #pragma unroll
        for (int p = 0; p < 4; p++) r[p] = 1.0f / acc[p];

        // ---- step 2: column-pair partials over this warp's 4 rows -----------
        uint64_t r2[4];
        #pragma unroll
        for (int p = 0; p < 4; p++) r2[p] = pack2(r[p], r[p]);
        #pragma unroll
        for (int q = 0; q < 8; q++) {
            uint64_t s2 = 0ull;
            #pragma unroll
            for (int p = 0; p < 4; p++) fma2(s2, r2[p], a2[p][q], s2);
            prow[warp][32 * q + lane] = s2;
        }
        __syncthreads();

        // ---- step 3: CTA-reduce partials, bulk-send owner segments ----------
        if (tid < 256) {
            uint64_t s2 = prow[0][tid];
            #pragma unroll
            for (int w = 1; w < 16; w++) add2(s2, s2, prow[w][tid]);
            myred[tid] = s2;
        }
        __syncthreads();   // myred ready
        if (tid < 8) {
            fence_async_shared();   // publish myred to async proxy
            blkcp_cluster(part_dst, part_src, SEG_BYTES, part_mbar_r);
        }

        // ---- step 4 (owners, tid<64): gather, compute c_own, bulk fan-out ---
        if (tid < 64) {
            mbar_wait_cluster(pm_addr, parity);
            if (tid == 0) mbar_expect_tx(pm_addr, HOP_TX);  // re-arm before c send
            float s = 0.0f;
            #pragma unroll
            for (int rr = 0; rr < 8; rr++) s += peer_part[rr][tid];
            c_own[tid] = 1.0f / s;
            asm volatile("bar.sync 1, 64;" ::: "memory");   // c_own complete
            if (tid < 8) {
                fence_async_shared();
                blkcp_cluster(c_dst, c_own_a, SEG_BYTES, c_mbar_r);
            }
        }

        // ---- step 5: everyone waits for the full new c -----------------------
        mbar_wait_cluster(cm_addr, parity);
        if (tid == 0) mbar_expect_tx(cm_addr, HOP_TX);  // re-arm (gated by the
        // __syncthreads above before next iteration's sends)
    }

    CLUSTER_SYNC();   // quiesce before teardown

    // ---------------- Epilogue: y_ij = r_i * A_ij * c_j ----------------------
    float* obase = out + ((size_t)bmat * NDIM + row0) * NDIM;
    #pragma unroll
    for (int p = 0; p < 4; p++) {
        float2* orow = (float2*)(obase + (size_t)p * NDIM) + lane;
        #pragma unroll
        for (int q = 0; q < 8; q++) {
            float alo, ahi; unpack2(alo, ahi, a2[p][q]);
            float2 cv = ((const float2*)c_smem)[32 * q + lane];
            float2 o;
            o.x = r[p] * alo * cv.x;
            o.y = r[p] * ahi * cv.y;
            orow[32 * q] = o;
        }
    }
}

extern "C" void kernel_launch(void* const* d_in, const int* in_sizes, int n_in,
                              void* d_out, int out_size)
{
    (void)in_sizes; (void)n_in; (void)out_size;
    const float* x = (const float*)d_in[0];
    float* out = (float*)d_out;
    // 16 matrices * 8 CTAs = 128 CTAs; __cluster_dims__(8) groups them per matrix.
    sinkhorn_kernel<<<128, 512>>>(x, out);
}

// round 7
// speedup vs baseline: 1.2110x; 1.1150x over previous
#include <cuda_runtime.h>
#include <cstdint>
#include <cstddef>

// Sinkhorn factored form: y = diag(r) * A * diag(c),  A = exp(x)+eps constant.
//   r <- 1/(A c);  c <- 1/(A^T r)
// 16 matrices of 512x512 fp32; one 8-CTA cluster per matrix; A register-resident.
// R7: R4 topology (two-hop scalar exchange) with: elected mbarrier waits
//     (1 or 32 threads instead of 512), all-b64 messages (512/CTA-iter instead
//     of 1024), fully parallel c fan-out, all mapa routes hoisted.

#define N_ITERS 100
#define NDIM 512
#define HOP_TX 2048   // per hop per CTA: 8 senders * 32 pairs * 8B

__device__ __forceinline__ uint32_t smem_u32(const void* p) {
    return (uint32_t)__cvta_generic_to_shared(p);
}
__device__ __forceinline__ uint32_t mapa_u32(uint32_t addr, uint32_t rank) {
    uint32_t r;
    asm("mapa.shared::cluster.u32 %0, %1, %2;" : "=r"(r) : "r"(addr), "r"(rank));
    return r;
}
__device__ __forceinline__ void fma2(uint64_t& d, uint64_t a, uint64_t b, uint64_t c) {
    asm("fma.rn.f32x2 %0, %1, %2, %3;" : "=l"(d) : "l"(a), "l"(b), "l"(c));
}
__device__ __forceinline__ void add2(uint64_t& d, uint64_t a, uint64_t b) {
    asm("add.rn.f32x2 %0, %1, %2;" : "=l"(d) : "l"(a), "l"(b));
}
__device__ __forceinline__ uint64_t pack2(float lo, float hi) {
    uint64_t r;
    asm("mov.b64 %0, {%1, %2};" : "=l"(r) : "f"(lo), "f"(hi));
    return r;
}
__device__ __forceinline__ void unpack2(float& lo, float& hi, uint64_t v) {
    asm("mov.b64 {%0, %1}, %2;" : "=f"(lo), "=f"(hi) : "l"(v));
}
__device__ __forceinline__ void st_async_b64(uint32_t dst, uint64_t v, uint32_t mbar) {
    asm volatile(
        "st.async.shared::cluster.mbarrier::complete_tx::bytes.b64 [%0], %1, [%2];"
        :: "r"(dst), "l"(v), "r"(mbar) : "memory");
}
__device__ __forceinline__ void mbar_init(uint32_t addr, uint32_t cnt) {
    asm volatile("mbarrier.init.shared.b64 [%0], %1;" :: "r"(addr), "r"(cnt) : "memory");
}
__device__ __forceinline__ void mbar_expect_tx(uint32_t addr, uint32_t bytes) {
    asm volatile("mbarrier.arrive.expect_tx.shared.b64 _, [%0], %1;"
                 :: "r"(addr), "r"(bytes) : "memory");
}
__device__ __forceinline__ void mbar_wait_cluster(uint32_t addr, uint32_t parity) {
    uint32_t done = 0;
    while (!done) {
        asm volatile(
            "{\n\t.reg .pred p;\n\t"
            "mbarrier.try_wait.parity.acquire.cluster.shared::cta.b64 p, [%1], %2, 0x989680;\n\t"
            "selp.b32 %0, 1, 0, p;\n\t}"
            : "=r"(done) : "r"(addr), "r"(parity) : "memory");
    }
}
#define CLUSTER_SYNC() do { \
    asm volatile("barrier.cluster.arrive.aligned;" ::: "memory"); \
    asm volatile("barrier.cluster.wait.aligned;"   ::: "memory"); } while (0)

__global__ void __launch_bounds__(512, 1) __cluster_dims__(8, 1, 1)
sinkhorn_kernel(const float* __restrict__ x, float* __restrict__ out)
{
    __shared__ __align__(16) float    c_smem[NDIM];      // column scaling c
    __shared__ __align__(16) uint64_t prow[16][256];     // per-warp col-pair partials
    __shared__ __align__(16) uint64_t peer_part[8][32];  // [src CTA][owned col pair]
    __shared__ __align__(16) uint64_t c_pair[32];        // new c pairs for owned cols
    __shared__ __align__(8)  uint64_t mbars[2];          // [0]=part, [1]=c

    const int tid  = threadIdx.x;
    const int warp = tid >> 5;            // 0..15
    const int lane = tid & 31;
    const int rank = blockIdx.x & 7;      // CTA rank in cluster = row block
    const int bmat = blockIdx.x >> 3;     // matrix index 0..15

    const int row0 = rank * 64 + warp * 4;      // 4 rows per warp
    // thread covers col pairs cp = 32q+lane (cols 2cp, 2cp+1), q = 0..7

    // ---------------- Prologue: A = exp(x) + eps, packed f32x2 in regs -------
    uint64_t a2[4][8];
    const float* xbase = x + ((size_t)bmat * NDIM + row0) * NDIM;
    #pragma unroll
    for (int p = 0; p < 4; p++) {
        const float2* xrow = (const float2*)(xbase + (size_t)p * NDIM) + lane;
        #pragma unroll
        for (int q = 0; q < 8; q++) {
            float2 v = xrow[32 * q];
            a2[p][q] = pack2(expf(v.x) + 0.001f, expf(v.y) + 0.001f);
        }
    }

    const uint32_t pm_addr  = smem_u32(&mbars[0]);
    const uint32_t cm_addr  = smem_u32(&mbars[1]);
    const uint32_t peer_a   = smem_u32(&peer_part[0][0]);
    const uint32_t c_smem_a = smem_u32(&c_smem[0]);

    c_smem[tid] = 1.0f;
    if (tid == 0) {
        mbar_init(pm_addr, 1);
        mbar_init(cm_addr, 1);
        mbar_expect_tx(pm_addr, HOP_TX);   // arm iteration 0
        mbar_expect_tx(cm_addr, HOP_TX);
    }
    __syncthreads();
    CLUSTER_SYNC();   // all barriers live + armed before any st.async

    // ---- loop-invariant message routes (threads 0..255) ---------------------
    // hop1: thread t sends reduced pair pr=t to owner CTA (pr>>5),
    //       landing at peer_part[rank][pr&31].
    // hop2: thread t sends c pair j=t>>3 to dest CTA (t&7),
    //       landing at c_smem[rank*64 + 2j .. +1].
    uint32_t h1_dst = 0, h1_mbar = 0, h2_dst = 0, h2_mbar = 0;
    if (tid < 256) {
        const uint32_t own = (uint32_t)(tid >> 5);
        h1_dst  = mapa_u32(peer_a + (uint32_t)((rank * 32 + (tid & 31)) * 8), own);
        h1_mbar = mapa_u32(pm_addr, own);
        const uint32_t dcta = (uint32_t)(tid & 7);
        const uint32_t j    = (uint32_t)(tid >> 3);
        h2_dst  = mapa_u32(c_smem_a + (uint32_t)(rank * 256 + j * 8), dcta);
        h2_mbar = mapa_u32(cm_addr, dcta);
    }

    const uint64_t* c2 = (const uint64_t*)c_smem;
    const uint64_t* pp = (const uint64_t*)&peer_part[0][0];
    float r[4];

    for (int it = 0; it < N_ITERS; it++) {
        const uint32_t parity = (uint32_t)(it & 1);

        // ---- step 1: row sums acc_i = (A c)_i ; r = 1/acc  (CTA-local) ----
        uint64_t acc2[4];
        #pragma unroll
        for (int p = 0; p < 4; p++) acc2[p] = 0ull;
        #pragma unroll
        for (int q = 0; q < 8; q++) {
            uint64_t cq = c2[32 * q + lane];
            #pragma unroll
            for (int p = 0; p < 4; p++) fma2(acc2[p], a2[p][q], cq, acc2[p]);
        }
        float acc[4];
        #pragma unroll
        for (int p = 0; p < 4; p++) {
            float lo, hi; unpack2(lo, hi, acc2[p]);
            acc[p] = lo + hi;
        }
        #pragma unroll
        for (int off = 16; off > 0; off >>= 1) {
            #pragma unroll
            for (int p = 0; p < 4; p++)
                acc[p] += __shfl_xor_sync(0xffffffffu, acc[p], off);
        }
        #pragma unroll
        for (int p = 0; p < 4; p++) r[p] = 1.0f / acc[p];

        // ---- step 2: column-pair partials over this warp's 4 rows -----------
        uint64_t r2[4];
        #pragma unroll
        for (int p = 0; p < 4; p++) r2[p] = pack2(r[p], r[p]);
        #pragma unroll
        for (int q = 0; q < 8; q++) {
            uint64_t s2 = 0ull;
            #pragma unroll
            for (int p = 0; p < 4; p++) fma2(s2, r2[p], a2[p][q], s2);
            prow[warp][32 * q + lane] = s2;
        }
        __syncthreads();

        if (tid < 256) {
            // ---- step 3: reduce 16 warps for pair tid, send b64 to owner ----
            uint64_t s2 = prow[0][tid];
            #pragma unroll
            for (int w = 1; w < 16; w++) add2(s2, s2, prow[w][tid]);
            st_async_b64(h1_dst, s2, h1_mbar);

            // ---- step 4: warp 0 gathers partials, computes c pairs ----------
            if (warp == 0) {
                mbar_wait_cluster(pm_addr, parity);     // 32 acquiring threads
                if (lane == 0) mbar_expect_tx(pm_addr, HOP_TX); // re-arm pre-send
                uint64_t s = pp[lane];
                #pragma unroll
                for (int rr = 1; rr < 8; rr++) add2(s, s, pp[rr * 32 + lane]);
                float lo, hi; unpack2(lo, hi, s);
                c_pair[lane] = pack2(1.0f / lo, 1.0f / hi);
            }
            asm volatile("bar.sync 1, 256;" ::: "memory");   // c_pair published

            // ---- step 5: fully parallel c fan-out (one send per thread) -----
            st_async_b64(h2_dst, c_pair[tid >> 3], h2_mbar);
        }

        // ---- step 6: elected wait for full new c, broadcast via barrier -----
        if (tid == 0) {
            mbar_wait_cluster(cm_addr, parity);
            mbar_expect_tx(cm_addr, HOP_TX);   // re-arm (next arrivals gated by
        }                                      //  our post-barrier hop1 sends)
        __syncthreads();
    }

    CLUSTER_SYNC();   // quiesce before teardown

    // ---------------- Epilogue: y_ij = r_i * A_ij * c_j ----------------------
    float* obase = out + ((size_t)bmat * NDIM + row0) * NDIM;
    #pragma unroll
    for (int p = 0; p < 4; p++) {
        float2* orow = (float2*)(obase + (size_t)p * NDIM) + lane;
        #pragma unroll
        for (int q = 0; q < 8; q++) {
            float alo, ahi; unpack2(alo, ahi, a2[p][q]);
            float2 cv = ((const float2*)c_smem)[32 * q + lane];
            float2 o;
            o.x = r[p] * alo * cv.x;
            o.y = r[p] * ahi * cv.y;
            orow[32 * q] = o;
        }
    }
}

extern "C" void kernel_launch(void* const* d_in, const int* in_sizes, int n_in,
                              void* d_out, int out_size)
{
    (void)in_sizes; (void)n_in; (void)out_size;
    const float* x = (const float*)d_in[0];
    float* out = (float*)d_out;
    // 16 matrices * 8 CTAs = 128 CTAs; __cluster_dims__(8) groups them per matrix.
    sinkhorn_kernel<<<128, 512>>>(x, out);
}